// round 4
// baseline (speedup 1.0000x reference)
#include <cuda_runtime.h>

#define T_SEQ 2048
#define B_SZ  512

// h1 scratch for the deferred dense head (134 MB)
__device__ __align__(16) float g_h1[(size_t)T_SEQ * B_SZ * 32];

typedef unsigned long long u64;

// ---------- packed f32x2 helpers ----------
__device__ __forceinline__ void unpack2(u64 v, float& a, float& b) {
    asm("mov.b64 {%0,%1},%2;" : "=f"(a), "=f"(b) : "l"(v));
}
__device__ __forceinline__ u64 fma2(u64 a, u64 b, u64 c) {
    u64 d; asm("fma.rn.f32x2 %0,%1,%2,%3;" : "=l"(d) : "l"(a), "l"(b), "l"(c)); return d;
}

// ---------- fast activations (MUFU ex2/rcp, ~1e-6 err — validated R1-R3) ----------
__device__ __forceinline__ float ex2f(float x) { float y; asm("ex2.approx.ftz.f32 %0,%1;" : "=f"(y) : "f"(x)); return y; }
__device__ __forceinline__ float rcpf(float x) { float y; asm("rcp.approx.ftz.f32 %0,%1;" : "=f"(y) : "f"(x)); return y; }
__device__ __forceinline__ float sigm(float x)  { return rcpf(1.f + ex2f(-1.4426950408889634f * x)); }
__device__ __forceinline__ float tanhf_(float x){ float e = ex2f(2.8853900817779268f * x); return 1.f - 2.f * rcpf(e + 1.f); }

// 4-gate matvec core: acc_g = {Sum_even, Sum_odd} of h_k * W[g][k], k = 0..31,
// consuming h as natural contiguous pairs (8x LDS.128, no duplication).
#define MATVEC4(hv, wg, a0, a1, a2, a3)                               \
    _Pragma("unroll")                                                 \
    for (int m = 0; m < 8; m++) {                                     \
        ulonglong2 h2 = (hv)[m];                                      \
        a0 = fma2(h2.x, (wg)[0][2*m], a0);                            \
        a1 = fma2(h2.x, (wg)[1][2*m], a1);                            \
        a2 = fma2(h2.x, (wg)[2][2*m], a2);                            \
        a3 = fma2(h2.x, (wg)[3][2*m], a3);                            \
        a0 = fma2(h2.y, (wg)[0][2*m+1], a0);                          \
        a1 = fma2(h2.y, (wg)[1][2*m+1], a1);                          \
        a2 = fma2(h2.y, (wg)[2][2*m+1], a2);                          \
        a3 = fma2(h2.y, (wg)[3][2*m+1], a3);                          \
    }

__device__ __forceinline__ float comb(u64 a, float extra) {
    float lo, hi; unpack2(a, lo, hi); return lo + hi + extra;
}

// =====================================================================
// Fused 2-layer LSTM (R2 skeleton: block-wide barrier, head separate).
// 3 specialized warps per batch element:
//   role 0: layer-0 cell              (h0[t] at tick n = t)
//   role 1: layer-1 input projection  (xp1[t] at tick n = t+1)
//   role 2: layer-1 cell              (h1[t] at tick n = t+2)
// Block = 4 elements x 3 roles = 12 warps, e = wid&3, role = wid>>2.
// =====================================================================
__global__ void __launch_bounds__(384, 1)
k_fused(const float* __restrict__ x,
        const float* __restrict__ Wih0, const float* __restrict__ Whh0,
        const float* __restrict__ bih0, const float* __restrict__ bhh0,
        const float* __restrict__ Wih1, const float* __restrict__ Whh1,
        const float* __restrict__ bih1, const float* __restrict__ bhh1)
{
    __shared__ __align__(16) float h0ring[4][2][32];   // plain h0 values
    __shared__ __align__(16) float pring[4][2][128];   // xp1 pre-activations
    __shared__ __align__(16) float h1buf[4][32];       // plain h1 values

    const int tid  = threadIdx.x;
    const int wid  = tid >> 5, j = tid & 31;
    const int e    = wid & 3;          // element slot in block
    const int role = wid >> 2;         // 0=L0 cell, 1=proj, 2=L1 cell
    const int b    = blockIdx.x * 4 + e;

    for (int i = tid; i < 4 * 2 * 32; i += 384) ((float*)h0ring)[i] = 0.f;
    for (int i = tid; i < 4 * 32;     i += 384) ((float*)h1buf)[i]  = 0.f;

    // per-role weight matrix: 4 gates x 16 contiguous k-pairs (u64 loads, no packing)
    const float* Wsrc = (role == 0) ? Whh0 : (role == 1) ? Wih1 : Whh1;
    const u64* Wu = reinterpret_cast<const u64*>(Wsrc);
    u64 wg[4][16];
#pragma unroll
    for (int g = 0; g < 4; g++)
#pragma unroll
        for (int p = 0; p < 16; p++)
            wg[g][p] = Wu[(g * 32 + j) * 16 + p];

    float wx[4] = {0, 0, 0, 0}, bs[4] = {0, 0, 0, 0};
    if (role == 0) {
#pragma unroll
        for (int g = 0; g < 4; g++) {
            wx[g] = Wih0[g * 32 + j];
            bs[g] = bih0[g * 32 + j] + bhh0[g * 32 + j];
        }
    } else if (role == 1) {
#pragma unroll
        for (int g = 0; g < 4; g++)
            bs[g] = bih1[g * 32 + j] + bhh1[g * 32 + j];
    }

    float c  = 0.f;                    // cell state (roles 0 and 2)
    float xt = x[b];                   // x[t=0]  (IN == 1)

    __syncthreads();

#pragma unroll 1
    for (int n = 0; n < T_SEQ + 2; n++) {
        if (role == 0) {
            if (n < T_SEQ) {
                float xn = (n + 1 < T_SEQ) ? x[(n + 1) * B_SZ + b] : 0.f;
                const ulonglong2* hv =
                    reinterpret_cast<const ulonglong2*>(h0ring[e][(n + 1) & 1]); // (n-1)&1
                u64 a0 = 0, a1 = 0, a2 = 0, a3 = 0;
                MATVEC4(hv, wg, a0, a1, a2, a3);
                float g0 = comb(a0, fmaf(xt, wx[0], bs[0]));
                float g1 = comb(a1, fmaf(xt, wx[1], bs[1]));
                float g2 = comb(a2, fmaf(xt, wx[2], bs[2]));
                float g3 = comb(a3, fmaf(xt, wx[3], bs[3]));
                float gi = sigm(g0), gf = sigm(g1), gg = tanhf_(g2), go = sigm(g3);
                c = gf * c + gi * gg;
                h0ring[e][n & 1][j] = go * tanhf_(c);
                xt = xn;
            }
        } else if (role == 1) {
            if (n >= 1 && n <= T_SEQ) {
                const ulonglong2* hv =
                    reinterpret_cast<const ulonglong2*>(h0ring[e][(n - 1) & 1]);
                u64 a0 = 0, a1 = 0, a2 = 0, a3 = 0;
                MATVEC4(hv, wg, a0, a1, a2, a3);
                float* pv = pring[e][(n - 1) & 1];
                pv[j]      = comb(a0, bs[0]);
                pv[32 + j] = comb(a1, bs[1]);
                pv[64 + j] = comb(a2, bs[2]);
                pv[96 + j] = comb(a3, bs[3]);
            }
        } else {
            if (n >= 2) {
                const int t = n - 2;
                const float* pv = pring[e][n & 1];     // slot (n-2)&1 == n&1
                float xp0 = pv[j], xp1v = pv[32 + j];
                float xp2 = pv[64 + j], xp3 = pv[96 + j];
                const ulonglong2* hv =
                    reinterpret_cast<const ulonglong2*>(h1buf[e]);
                u64 a0 = 0, a1 = 0, a2 = 0, a3 = 0;
                MATVEC4(hv, wg, a0, a1, a2, a3);
                __syncwarp();   // all lanes done reading h1buf before overwrite
                float g0 = comb(a0, xp0), g1 = comb(a1, xp1v);
                float g2 = comb(a2, xp2), g3 = comb(a3, xp3);
                float gi = sigm(g0), gf = sigm(g1), gg = tanhf_(g2), go = sigm(g3);
                c = gf * c + gi * gg;
                float h = go * tanhf_(c);
                h1buf[e][j] = h;
                g_h1[(size_t)t * (B_SZ * 32) + b * 32 + j] = h;   // coalesced
            }
        }
        __syncthreads();
    }
}

// =====================================================================
// Dense head: out[t,b] = sum_j h1[t,b,j]*Wd[j] + bd. Memory-bound (~30us).
// =====================================================================
__global__ void __launch_bounds__(256)
k_head(const float* __restrict__ Wd, const float* __restrict__ bd,
       float* __restrict__ out)
{
    const int gw = blockIdx.x * 8 + (threadIdx.x >> 5);
    const int j  = threadIdx.x & 31;
    const size_t r = (size_t)gw * 4 + (j >> 3);
    const int q  = j & 7;

    float4 h = reinterpret_cast<const float4*>(g_h1)[r * 8 + q];
    float4 w = reinterpret_cast<const float4*>(Wd)[q];
    float s = h.x * w.x + h.y * w.y + h.z * w.z + h.w * w.w;
    s += __shfl_xor_sync(0xffffffffu, s, 1);
    s += __shfl_xor_sync(0xffffffffu, s, 2);
    s += __shfl_xor_sync(0xffffffffu, s, 4);
    if (q == 0) out[r] = s + bd[0];
}

// =====================================================================
extern "C" void kernel_launch(void* const* d_in, const int* in_sizes, int n_in,
                              void* d_out, int out_size)
{
    const float* x    = (const float*)d_in[0];
    const float* Wih0 = (const float*)d_in[1];
    const float* Whh0 = (const float*)d_in[2];
    const float* bih0 = (const float*)d_in[3];
    const float* bhh0 = (const float*)d_in[4];
    const float* Wih1 = (const float*)d_in[5];
    const float* Whh1 = (const float*)d_in[6];
    const float* bih1 = (const float*)d_in[7];
    const float* bhh1 = (const float*)d_in[8];
    const float* Wd   = (const float*)d_in[9];
    const float* bd   = (const float*)d_in[10];

    k_fused<<<128, 384>>>(x, Wih0, Whh0, bih0, bhh0, Wih1, Whh1, bih1, bhh1);
    k_head<<<32768, 256>>>(Wd, bd, (float*)d_out);
}

// round 5
// speedup vs baseline: 1.4283x; 1.4283x over previous
#include <cuda_runtime.h>

#define T_SEQ 2048
#define B_SZ  512

// h1 scratch for the deferred dense head (134 MB)
__device__ __align__(16) float g_h1[(size_t)T_SEQ * B_SZ * 32];

typedef unsigned long long u64;

// ---------- packed f32x2 helpers ----------
__device__ __forceinline__ u64 pack2(float a, float b) {
    u64 d; asm("mov.b64 %0,{%1,%2};" : "=l"(d) : "f"(a), "f"(b)); return d;
}
__device__ __forceinline__ void unpack2(u64 v, float& a, float& b) {
    asm("mov.b64 {%0,%1},%2;" : "=f"(a), "=f"(b) : "l"(v));
}
__device__ __forceinline__ u64 fma2(u64 a, u64 b, u64 c) {
    u64 d; asm("fma.rn.f32x2 %0,%1,%2,%3;" : "=l"(d) : "l"(a), "l"(b), "l"(c)); return d;
}

// ---------- fast activations (MUFU ex2/rcp, ~1e-6 err — validated R1-R4) ----------
__device__ __forceinline__ float ex2f(float x) { float y; asm("ex2.approx.ftz.f32 %0,%1;" : "=f"(y) : "f"(x)); return y; }
__device__ __forceinline__ float rcpf(float x) { float y; asm("rcp.approx.ftz.f32 %0,%1;" : "=f"(y) : "f"(x)); return y; }
__device__ __forceinline__ float sigm(float x)  { return rcpf(1.f + ex2f(-1.4426950408889634f * x)); }
__device__ __forceinline__ float tanhf_(float x){ float e = ex2f(2.8853900817779268f * x); return 1.f - 2.f * rcpf(e + 1.f); }

// =====================================================================
// Fused 2-layer LSTM. ONE TRIO PER BLOCK (the R2 inner loop, exactly):
//   warp 0: layer-0 cell              (h0[t] at tick n = t)
//   warp 1: layer-1 input projection  (xp1[t] at tick n = t+1)
//   warp 2: layer-1 cell              (h1[t] at tick n = t+2)
// grid = 512 blocks x 96 threads; 4 independent blocks co-reside per SM
// (forced by __launch_bounds__(96,4)) and drift freely — one trio's FMA
// burst hides another trio's activation-tail / LDS / barrier stalls.
// =====================================================================
__global__ void __launch_bounds__(96, 4)
k_fused(const float* __restrict__ x,
        const float* __restrict__ Wih0, const float* __restrict__ Whh0,
        const float* __restrict__ bih0, const float* __restrict__ bhh0,
        const float* __restrict__ Wih1, const float* __restrict__ Whh1,
        const float* __restrict__ bih1, const float* __restrict__ bhh1)
{
    __shared__ __align__(16) float h0ring[2][64];   // duplicated {h,h} pairs
    __shared__ __align__(16) u64   pring[2][64];    // [j]={i,f}, [32+j]={g,o}
    __shared__ __align__(16) float h1ring[2][64];   // duplicated {h,h} pairs

    const int tid  = threadIdx.x;
    const int role = tid >> 5, j = tid & 31;
    const int b    = blockIdx.x;

    // zero initial hidden states (both ring slots)
    for (int i = tid; i < 2 * 64; i += 96) {
        ((float*)h0ring)[i] = 0.f;
        ((float*)h1ring)[i] = 0.f;
    }

    // per-role weight matrix -> 64 u64 regs of gate-pair columns
    const float* Wsrc = (role == 0) ? Whh0 : (role == 1) ? Wih1 : Whh1;
    u64 w_if[32], w_go[32];
#pragma unroll
    for (int k = 0; k < 32; k++) {
        w_if[k] = pack2(Wsrc[j * 32 + k],        Wsrc[(32 + j) * 32 + k]);
        w_go[k] = pack2(Wsrc[(64 + j) * 32 + k], Wsrc[(96 + j) * 32 + k]);
    }

    u64 wx_if = 0, wx_go = 0, bs_if = 0, bs_go = 0;
    if (role == 0) {
        wx_if = pack2(Wih0[j],      Wih0[32 + j]);
        wx_go = pack2(Wih0[64 + j], Wih0[96 + j]);
        bs_if = pack2(bih0[j] + bhh0[j],           bih0[32 + j] + bhh0[32 + j]);
        bs_go = pack2(bih0[64 + j] + bhh0[64 + j], bih0[96 + j] + bhh0[96 + j]);
    } else if (role == 1) {
        bs_if = pack2(bih1[j] + bhh1[j],           bih1[32 + j] + bhh1[32 + j]);
        bs_go = pack2(bih1[64 + j] + bhh1[64 + j], bih1[96 + j] + bhh1[96 + j]);
    }

    float c  = 0.f;                    // cell state (roles 0 and 2)
    float xt = x[b];                   // x[t=0]  (IN == 1)

    __syncthreads();                   // init visible

#pragma unroll 1
    for (int n = 0; n < T_SEQ + 2; n++) {
        if (role == 0) {
            if (n < T_SEQ) {
                float xn = (n + 1 < T_SEQ) ? x[(n + 1) * B_SZ + b] : 0.f;
                u64 xs  = pack2(xt, xt);
                u64 aif = fma2(xs, wx_if, bs_if);
                u64 ago = fma2(xs, wx_go, bs_go);
                const u64* hv = reinterpret_cast<const u64*>(h0ring[(n + 1) & 1]); // (n-1)&1
#pragma unroll
                for (int k = 0; k < 32; k++) {
                    u64 h2 = hv[k];
                    aif = fma2(h2, w_if[k], aif);
                    ago = fma2(h2, w_go[k], ago);
                }
                float gi, gf, gg, go;
                unpack2(aif, gi, gf); unpack2(ago, gg, go);
                gi = sigm(gi); gf = sigm(gf); gg = tanhf_(gg); go = sigm(go);
                c = gf * c + gi * gg;
                float h = go * tanhf_(c);
                reinterpret_cast<u64*>(h0ring[n & 1])[j] = pack2(h, h);
                xt = xn;
            }
        } else if (role == 1) {
            if (n >= 1 && n <= T_SEQ) {
                const u64* hv = reinterpret_cast<const u64*>(h0ring[(n - 1) & 1]);
                u64 aif = bs_if, ago = bs_go;
#pragma unroll
                for (int k = 0; k < 32; k++) {
                    u64 h2 = hv[k];
                    aif = fma2(h2, w_if[k], aif);
                    ago = fma2(h2, w_go[k], ago);
                }
                pring[(n - 1) & 1][j]      = aif;
                pring[(n - 1) & 1][32 + j] = ago;
            }
        } else {
            if (n >= 2) {
                const int t = n - 2;
                const u64* pv = pring[n & 1];          // slot (n-2)&1 == n&1
                u64 aif = pv[j];
                u64 ago = pv[32 + j];
                const u64* hv = reinterpret_cast<const u64*>(h1ring[(n + 1) & 1]); // (n-1)&1
#pragma unroll
                for (int k = 0; k < 32; k++) {
                    u64 h2 = hv[k];
                    aif = fma2(h2, w_if[k], aif);
                    ago = fma2(h2, w_go[k], ago);
                }
                float gi, gf, gg, go;
                unpack2(aif, gi, gf); unpack2(ago, gg, go);
                gi = sigm(gi); gf = sigm(gf); gg = tanhf_(gg); go = sigm(go);
                c = gf * c + gi * gg;
                float h = go * tanhf_(c);
                reinterpret_cast<u64*>(h1ring[n & 1])[j] = pack2(h, h);
                g_h1[(size_t)t * (B_SZ * 32) + b * 32 + j] = h;   // coalesced
            }
        }
        __syncthreads();               // 3-warp barrier, this trio only
    }
}

// =====================================================================
// Dense head: out[t,b] = sum_j h1[t,b,j]*Wd[j] + bd. Memory-bound (~30us).
// =====================================================================
__global__ void __launch_bounds__(256)
k_head(const float* __restrict__ Wd, const float* __restrict__ bd,
       float* __restrict__ out)
{
    const int gw = blockIdx.x * 8 + (threadIdx.x >> 5);
    const int j  = threadIdx.x & 31;
    const size_t r = (size_t)gw * 4 + (j >> 3);
    const int q  = j & 7;

    float4 h = reinterpret_cast<const float4*>(g_h1)[r * 8 + q];
    float4 w = reinterpret_cast<const float4*>(Wd)[q];
    float s = h.x * w.x + h.y * w.y + h.z * w.z + h.w * w.w;
    s += __shfl_xor_sync(0xffffffffu, s, 1);
    s += __shfl_xor_sync(0xffffffffu, s, 2);
    s += __shfl_xor_sync(0xffffffffu, s, 4);
    if (q == 0) out[r] = s + bd[0];
}

// =====================================================================
extern "C" void kernel_launch(void* const* d_in, const int* in_sizes, int n_in,
                              void* d_out, int out_size)
{
    const float* x    = (const float*)d_in[0];
    const float* Wih0 = (const float*)d_in[1];
    const float* Whh0 = (const float*)d_in[2];
    const float* bih0 = (const float*)d_in[3];
    const float* bhh0 = (const float*)d_in[4];
    const float* Wih1 = (const float*)d_in[5];
    const float* Whh1 = (const float*)d_in[6];
    const float* bih1 = (const float*)d_in[7];
    const float* bhh1 = (const float*)d_in[8];
    const float* Wd   = (const float*)d_in[9];
    const float* bd   = (const float*)d_in[10];

    k_fused<<<512, 96>>>(x, Wih0, Whh0, bih0, bhh0, Wih1, Whh1, bih1, bhh1);
    k_head<<<32768, 256>>>(Wd, bd, (float*)d_out);
}

// round 6
// speedup vs baseline: 1.5296x; 1.0709x over previous
#include <cuda_runtime.h>

#define T_SEQ 2048
#define B_SZ  512

// h1 scratch for the deferred dense head (134 MB)
__device__ __align__(16) float g_h1[(size_t)T_SEQ * B_SZ * 32];

typedef unsigned long long u64;

// ---------- packed f32x2 helpers ----------
__device__ __forceinline__ u64 pack2(float a, float b) {
    u64 d; asm("mov.b64 %0,{%1,%2};" : "=l"(d) : "f"(a), "f"(b)); return d;
}
__device__ __forceinline__ void unpack2(u64 v, float& a, float& b) {
    asm("mov.b64 {%0,%1},%2;" : "=f"(a), "=f"(b) : "l"(v));
}
__device__ __forceinline__ u64 fma2(u64 a, u64 b, u64 c) {
    u64 d; asm("fma.rn.f32x2 %0,%1,%2,%3;" : "=l"(d) : "l"(a), "l"(b), "l"(c)); return d;
}

// ---------- activations via HW MUFU tanh (sm_75+), 1 MUFU each ----------
__device__ __forceinline__ float htanh(float x) {
    float y; asm("tanh.approx.f32 %0,%1;" : "=f"(y) : "f"(x)); return y;
}
__device__ __forceinline__ float sigm(float x)  { return fmaf(htanh(0.5f * x), 0.5f, 0.5f); }
__device__ __forceinline__ float tanhf_(float x){ return htanh(x); }

// =====================================================================
// Fused 2-layer LSTM. One trio (3 warps) per block, R5 skeleton.
//   role 0: layer-0 cell              (h0[t] at tick n = t)
//   role 1: layer-1 input projection  (xp1[t] at tick n = t+1)
//   role 2: layer-1 cell              (h1[t] at tick n = t+2)
// role = (wid + blockIdx) % 3: co-resident blocks place DIFFERENT roles
// on each SMSP, so MUFU-heavy cell warps mix with MUFU-free proj warps.
// h rings read as 16x LDS.128 (ulonglong2 of duplicated {h,h} pairs).
// =====================================================================
__global__ void __launch_bounds__(96, 4)
k_fused(const float* __restrict__ x,
        const float* __restrict__ Wih0, const float* __restrict__ Whh0,
        const float* __restrict__ bih0, const float* __restrict__ bhh0,
        const float* __restrict__ Wih1, const float* __restrict__ Whh1,
        const float* __restrict__ bih1, const float* __restrict__ bhh1)
{
    __shared__ __align__(16) float h0ring[2][64];   // duplicated {h,h} pairs
    __shared__ __align__(16) u64   pring[2][64];    // [j]={i,f}, [32+j]={g,o}
    __shared__ __align__(16) float h1ring[2][64];   // duplicated {h,h} pairs

    const int tid  = threadIdx.x;
    const int wid  = tid >> 5, j = tid & 31;
    const int role = (wid + blockIdx.x) % 3;        // rotated role mapping
    const int b    = blockIdx.x;

    // zero initial hidden states (both ring slots)
    for (int i = tid; i < 2 * 64; i += 96) {
        ((float*)h0ring)[i] = 0.f;
        ((float*)h1ring)[i] = 0.f;
    }

    // per-role weight matrix -> 64 u64 regs of gate-pair columns
    const float* Wsrc = (role == 0) ? Whh0 : (role == 1) ? Wih1 : Whh1;
    u64 w_if[32], w_go[32];
#pragma unroll
    for (int k = 0; k < 32; k++) {
        w_if[k] = pack2(Wsrc[j * 32 + k],        Wsrc[(32 + j) * 32 + k]);
        w_go[k] = pack2(Wsrc[(64 + j) * 32 + k], Wsrc[(96 + j) * 32 + k]);
    }

    u64 wx_if = 0, wx_go = 0, bs_if = 0, bs_go = 0;
    if (role == 0) {
        wx_if = pack2(Wih0[j],      Wih0[32 + j]);
        wx_go = pack2(Wih0[64 + j], Wih0[96 + j]);
        bs_if = pack2(bih0[j] + bhh0[j],           bih0[32 + j] + bhh0[32 + j]);
        bs_go = pack2(bih0[64 + j] + bhh0[64 + j], bih0[96 + j] + bhh0[96 + j]);
    } else if (role == 1) {
        bs_if = pack2(bih1[j] + bhh1[j],           bih1[32 + j] + bhh1[32 + j]);
        bs_go = pack2(bih1[64 + j] + bhh1[64 + j], bih1[96 + j] + bhh1[96 + j]);
    }

    float c  = 0.f;                    // cell state (roles 0 and 2)
    float xt = x[b];                   // x[t=0]  (IN == 1)

    __syncthreads();                   // init visible

#pragma unroll 1
    for (int n = 0; n < T_SEQ + 2; n++) {
        if (role == 0) {
            if (n < T_SEQ) {
                float xn = (n + 1 < T_SEQ) ? x[(n + 1) * B_SZ + b] : 0.f;
                u64 xs  = pack2(xt, xt);
                u64 aif = fma2(xs, wx_if, bs_if);
                u64 ago = fma2(xs, wx_go, bs_go);
                const ulonglong2* hv =
                    reinterpret_cast<const ulonglong2*>(h0ring[(n + 1) & 1]); // (n-1)&1
#pragma unroll
                for (int m = 0; m < 16; m++) {
                    ulonglong2 h2 = hv[m];              // {h2m,h2m},{h2m+1,h2m+1}
                    aif = fma2(h2.x, w_if[2*m],   aif);
                    ago = fma2(h2.x, w_go[2*m],   ago);
                    aif = fma2(h2.y, w_if[2*m+1], aif);
                    ago = fma2(h2.y, w_go[2*m+1], ago);
                }
                float gi, gf, gg, go;
                unpack2(aif, gi, gf); unpack2(ago, gg, go);
                gi = sigm(gi); gf = sigm(gf); gg = tanhf_(gg); go = sigm(go);
                c = gf * c + gi * gg;
                float h = go * tanhf_(c);
                reinterpret_cast<u64*>(h0ring[n & 1])[j] = pack2(h, h);
                xt = xn;
            }
        } else if (role == 1) {
            if (n >= 1 && n <= T_SEQ) {
                const ulonglong2* hv =
                    reinterpret_cast<const ulonglong2*>(h0ring[(n - 1) & 1]);
                u64 aif = bs_if, ago = bs_go;
#pragma unroll
                for (int m = 0; m < 16; m++) {
                    ulonglong2 h2 = hv[m];
                    aif = fma2(h2.x, w_if[2*m],   aif);
                    ago = fma2(h2.x, w_go[2*m],   ago);
                    aif = fma2(h2.y, w_if[2*m+1], aif);
                    ago = fma2(h2.y, w_go[2*m+1], ago);
                }
                pring[(n - 1) & 1][j]      = aif;
                pring[(n - 1) & 1][32 + j] = ago;
            }
        } else {
            if (n >= 2) {
                const int t = n - 2;
                const u64* pv = pring[n & 1];          // slot (n-2)&1 == n&1
                u64 aif = pv[j];
                u64 ago = pv[32 + j];
                const ulonglong2* hv =
                    reinterpret_cast<const ulonglong2*>(h1ring[(n + 1) & 1]); // (n-1)&1
#pragma unroll
                for (int m = 0; m < 16; m++) {
                    ulonglong2 h2 = hv[m];
                    aif = fma2(h2.x, w_if[2*m],   aif);
                    ago = fma2(h2.x, w_go[2*m],   ago);
                    aif = fma2(h2.y, w_if[2*m+1], aif);
                    ago = fma2(h2.y, w_go[2*m+1], ago);
                }
                float gi, gf, gg, go;
                unpack2(aif, gi, gf); unpack2(ago, gg, go);
                gi = sigm(gi); gf = sigm(gf); gg = tanhf_(gg); go = sigm(go);
                c = gf * c + gi * gg;
                float h = go * tanhf_(c);
                reinterpret_cast<u64*>(h1ring[n & 1])[j] = pack2(h, h);
                g_h1[(size_t)t * (B_SZ * 32) + b * 32 + j] = h;   // coalesced
            }
        }
        __syncthreads();               // 3-warp barrier, this trio only
    }
}

// =====================================================================
// Dense head: out[t,b] = sum_j h1[t,b,j]*Wd[j] + bd. Memory-bound (~30us).
// =====================================================================
__global__ void __launch_bounds__(256)
k_head(const float* __restrict__ Wd, const float* __restrict__ bd,
       float* __restrict__ out)
{
    const int gw = blockIdx.x * 8 + (threadIdx.x >> 5);
    const int j  = threadIdx.x & 31;
    const size_t r = (size_t)gw * 4 + (j >> 3);
    const int q  = j & 7;

    float4 h = reinterpret_cast<const float4*>(g_h1)[r * 8 + q];
    float4 w = reinterpret_cast<const float4*>(Wd)[q];
    float s = h.x * w.x + h.y * w.y + h.z * w.z + h.w * w.w;
    s += __shfl_xor_sync(0xffffffffu, s, 1);
    s += __shfl_xor_sync(0xffffffffu, s, 2);
    s += __shfl_xor_sync(0xffffffffu, s, 4);
    if (q == 0) out[r] = s + bd[0];
}

// =====================================================================
extern "C" void kernel_launch(void* const* d_in, const int* in_sizes, int n_in,
                              void* d_out, int out_size)
{
    const float* x    = (const float*)d_in[0];
    const float* Wih0 = (const float*)d_in[1];
    const float* Whh0 = (const float*)d_in[2];
    const float* bih0 = (const float*)d_in[3];
    const float* bhh0 = (const float*)d_in[4];
    const float* Wih1 = (const float*)d_in[5];
    const float* Whh1 = (const float*)d_in[6];
    const float* bih1 = (const float*)d_in[7];
    const float* bhh1 = (const float*)d_in[8];
    const float* Wd   = (const float*)d_in[9];
    const float* bd   = (const float*)d_in[10];

    k_fused<<<512, 96>>>(x, Wih0, Whh0, bih0, bhh0, Wih1, Whh1, bih1, bhh1);
    k_head<<<32768, 256>>>(Wd, bd, (float*)d_out);
}